// round 1
// baseline (speedup 1.0000x reference)
#include <cuda_runtime.h>

// BiAttention (BiDAF) layer for N=64, T=1024, J=64, D2=200.
// G = concat([H, U_, H*U_, H*H_], -1)  -> (64, 1024, 800) fp32.

#define NB   64
#define TT   1024
#define JJ   64
#define DD   200
#define NEGV (-10000000.0f)

// scratch (device globals; no allocation allowed)
__device__ float g_Smax[NB * TT];
__device__ float g_Hbar[NB * DD];

// ---- shared layout for main kernel (floats) ----
#define HS_STRIDE 212
#define PS_STRIDE 132
#define OFF_HS   0                    // 128*212 = 27136
#define OFF_UO   27136                // 64*212  = 13568
#define OFF_PST  40704                // 64*132  = 8448
#define OFF_HWH  49152                // 128
#define OFF_UWU  49280                // 64
#define OFF_QM   49344                // 64
#define OFF_W    49408                // 600
#define SMEM_FLOATS 50008
#define SMEM_BYTES  (SMEM_FLOATS * 4) // 200032

typedef unsigned long long ull;

__device__ __forceinline__ void fma2(ull& acc, ull a, ull b) {
    asm("fma.rn.f32x2 %0, %1, %2, %0;" : "+l"(acc) : "l"(a), "l"(b));
}
__device__ __forceinline__ ull dup2(float x) {
    ull r; unsigned xi = __float_as_uint(x);
    asm("mov.b64 %0, {%1, %1};" : "=l"(r) : "r"(xi));
    return r;
}
__device__ __forceinline__ float lo32(ull v) { return __uint_as_float((unsigned)v); }
__device__ __forceinline__ float hi32(ull v) { return __uint_as_float((unsigned)(v >> 32)); }

__global__ void __launch_bounds__(256, 1)
bi_attn_main(const float* __restrict__ H, const float* __restrict__ U,
             const float* __restrict__ q_mask, const float* __restrict__ wv,
             const float* __restrict__ bptr, float* __restrict__ G)
{
    extern __shared__ float sm[];
    float* sHs  = sm + OFF_HS;   // scaled H tile [128][212] (h * w_hu), k-contiguous
    float* sUo  = sm + OFF_UO;   // U tile [64][212], k-contiguous
    float* sPsT = sm + OFF_PST;  // softmax probs transposed [64][132] (j-major)
    float* sHwh = sm + OFF_HWH;
    float* sUwu = sm + OFF_UWU;
    float* sQm  = sm + OFF_QM;
    float* sW   = sm + OFF_W;

    const int tid = threadIdx.x;
    const int n   = blockIdx.y;
    const int m0  = blockIdx.x * 128;

    for (int i = tid; i < 600; i += 256) sW[i] = wv[i];
    for (int i = tid; i < 64;  i += 256) sQm[i] = q_mask[n * 64 + i];
    __syncthreads();

    const float bval = bptr[0];

    // ---- stage H tile (scaled by w_hu) + row dots Hwh = h . w_h ----
    {
        const int kg = tid & 7;        // k-chunk group
        const int mb = tid >> 3;       // 0..31
        #pragma unroll 1
        for (int r = 0; r < 4; r++) {
            const int m = mb + 32 * r;
            const float* hrow = H + (size_t)(n * 1024 + m0 + m) * 200;
            float hwh = 0.f;
            #pragma unroll
            for (int c = kg; c < 50; c += 8) {
                float4 h4   = *(const float4*)(hrow + c * 4);
                float4 wh4  = *(const float4*)(sW + c * 4);
                float4 whu4 = *(const float4*)(sW + 400 + c * 4);
                hwh += h4.x * wh4.x + h4.y * wh4.y + h4.z * wh4.z + h4.w * wh4.w;
                float4 hs;
                hs.x = h4.x * whu4.x; hs.y = h4.y * whu4.y;
                hs.z = h4.z * whu4.z; hs.w = h4.w * whu4.w;
                *(float4*)(sHs + m * HS_STRIDE + c * 4) = hs;
            }
            hwh += __shfl_xor_sync(0xffffffffu, hwh, 1);
            hwh += __shfl_xor_sync(0xffffffffu, hwh, 2);
            hwh += __shfl_xor_sync(0xffffffffu, hwh, 4);
            if (kg == 0) sHwh[m] = hwh;
        }
    }
    // ---- stage U tile + Uwu = u . w_u ----
    {
        const int kg = tid & 7;
        const int jb = tid >> 3;
        #pragma unroll 1
        for (int r = 0; r < 2; r++) {
            const int j = jb + 32 * r;
            const float* urow = U + (size_t)(n * 64 + j) * 200;
            float uwu = 0.f;
            #pragma unroll
            for (int c = kg; c < 50; c += 8) {
                float4 u4  = *(const float4*)(urow + c * 4);
                float4 wu4 = *(const float4*)(sW + 200 + c * 4);
                uwu += u4.x * wu4.x + u4.y * wu4.y + u4.z * wu4.z + u4.w * wu4.w;
                *(float4*)(sUo + j * HS_STRIDE + c * 4) = u4;
            }
            uwu += __shfl_xor_sync(0xffffffffu, uwu, 1);
            uwu += __shfl_xor_sync(0xffffffffu, uwu, 2);
            uwu += __shfl_xor_sync(0xffffffffu, uwu, 4);
            if (kg == 0) sUwu[j] = uwu;
        }
    }
    __syncthreads();

    const int tm = tid >> 3;   // 0..31  -> rows m = tm*4 .. tm*4+3
    const int tj = tid & 7;    // 0..7   -> cols j = tj + 8*jj

    // ---- Phase A: S-tile GEMM (128x64) with f32x2 over k-pairs ----
    ull acc[4][8];
    #pragma unroll
    for (int i = 0; i < 4; i++)
        #pragma unroll
        for (int jj = 0; jj < 8; jj++) acc[i][jj] = 0ull;

    const float* hsBase = sHs + tm * 4 * HS_STRIDE;
    const float* uoBase = sUo + tj * HS_STRIDE;
    #pragma unroll 2
    for (int k = 0; k < 200; k += 2) {
        ull a0 = *(const ull*)(hsBase + k);
        ull a1 = *(const ull*)(hsBase + HS_STRIDE + k);
        ull a2 = *(const ull*)(hsBase + 2 * HS_STRIDE + k);
        ull a3 = *(const ull*)(hsBase + 3 * HS_STRIDE + k);
        #pragma unroll
        for (int jj = 0; jj < 8; jj++) {
            ull bv = *(const ull*)(uoBase + jj * (8 * HS_STRIDE) + k);
            fma2(acc[0][jj], a0, bv);
            fma2(acc[1][jj], a1, bv);
            fma2(acc[2][jj], a2, bv);
            fma2(acc[3][jj], a3, bv);
        }
    }

    // ---- Phase B: masked softmax over j (row owned by 8 lanes tj) ----
    #pragma unroll 1
    for (int i = 0; i < 4; i++) {
        const int m = tm * 4 + i;
        const float hwh = sHwh[m];
        float vmv[8], qv[8];
        float mx = -3.4e38f, smx = -3.4e38f;
        #pragma unroll
        for (int jj = 0; jj < 8; jj++) {
            const int j = tj + 8 * jj;
            const ull v = acc[i][jj];
            const float s = lo32(v) + hi32(v) + hwh + sUwu[j] + bval;
            const float q = sQm[j];
            const float vm = s * q;
            vmv[jj] = vm; qv[jj] = q;
            mx  = fmaxf(mx, vm);
            smx = fmaxf(smx, (q != 0.f) ? s : NEGV);
        }
        mx  = fmaxf(mx,  __shfl_xor_sync(0xffffffffu, mx, 1));
        mx  = fmaxf(mx,  __shfl_xor_sync(0xffffffffu, mx, 2));
        mx  = fmaxf(mx,  __shfl_xor_sync(0xffffffffu, mx, 4));
        smx = fmaxf(smx, __shfl_xor_sync(0xffffffffu, smx, 1));
        smx = fmaxf(smx, __shfl_xor_sync(0xffffffffu, smx, 2));
        smx = fmaxf(smx, __shfl_xor_sync(0xffffffffu, smx, 4));
        float E = 0.f, M = 0.f, ev[8];
        #pragma unroll
        for (int jj = 0; jj < 8; jj++) {
            const float e = __expf(vmv[jj] - mx);
            ev[jj] = e; E += e; M += e * qv[jj];
        }
        E += __shfl_xor_sync(0xffffffffu, E, 1);
        E += __shfl_xor_sync(0xffffffffu, E, 2);
        E += __shfl_xor_sync(0xffffffffu, E, 4);
        M += __shfl_xor_sync(0xffffffffu, M, 1);
        M += __shfl_xor_sync(0xffffffffu, M, 2);
        M += __shfl_xor_sync(0xffffffffu, M, 4);
        const float inv = 1.0f / (M + 1e-13f * E);
        #pragma unroll
        for (int jj = 0; jj < 8; jj++)
            sPsT[(tj + 8 * jj) * PS_STRIDE + m] = ev[jj] * qv[jj] * inv;
        if (tj == 0) g_Smax[(n << 10) + m0 + m] = smx;
    }
    __syncthreads();

    // ---- Phase C: U_ = P @ U, write G[:,:,0:600] ----
    const float* Hrow0 = H + (size_t)(n * 1024 + m0 + tm * 4) * 200;
    float*       Grow0 = G + (size_t)(n * 1024 + m0 + tm * 4) * 800;
    const float* psBase = sPsT + tm * 4;

    #pragma unroll 1
    for (int pass = 0; pass < 7; pass++) {
        const int chunk = pass * 8 + tj;     // 0..55, valid < 50
        const int d0 = (chunk < 50) ? chunk * 4 : 0;
        ull acc0[4], acc1[4];
        #pragma unroll
        for (int i = 0; i < 4; i++) { acc0[i] = 0ull; acc1[i] = 0ull; }
        const float* uoD = sUo + d0;
        #pragma unroll 4
        for (int j = 0; j < 64; j++) {
            const float4 a4 = *(const float4*)(psBase + j * PS_STRIDE);
            const ull b0 = *(const ull*)(uoD + j * HS_STRIDE);
            const ull b1 = *(const ull*)(uoD + j * HS_STRIDE + 2);
            const ull dx = dup2(a4.x); fma2(acc0[0], dx, b0); fma2(acc1[0], dx, b1);
            const ull dy = dup2(a4.y); fma2(acc0[1], dy, b0); fma2(acc1[1], dy, b1);
            const ull dz = dup2(a4.z); fma2(acc0[2], dz, b0); fma2(acc1[2], dz, b1);
            const ull dw = dup2(a4.w); fma2(acc0[3], dw, b0); fma2(acc1[3], dw, b1);
        }
        if (chunk < 50) {
            #pragma unroll
            for (int i = 0; i < 4; i++) {
                float4 uo;
                uo.x = lo32(acc0[i]); uo.y = hi32(acc0[i]);
                uo.z = lo32(acc1[i]); uo.w = hi32(acc1[i]);
                const float4 h4 = *(const float4*)(Hrow0 + i * 200 + d0);
                float* gp = Grow0 + (size_t)i * 800;
                *(float4*)(gp + d0) = h4;
                *(float4*)(gp + 200 + d0) = uo;
                float4 hu;
                hu.x = h4.x * uo.x; hu.y = h4.y * uo.y;
                hu.z = h4.z * uo.z; hu.w = h4.w * uo.w;
                *(float4*)(gp + 400 + d0) = hu;
            }
        }
    }
}

// ---- kernel 2: a = masked_softmax(S_max, c_mask) over t ; Hbar = a @ H ----
__global__ void __launch_bounds__(256)
bi_attn_ctx(const float* __restrict__ H, const float* __restrict__ c_mask)
{
    __shared__ float sa[1024];
    __shared__ float redA[8], redB[8], redC[8];
    const int n = blockIdx.x, tid = threadIdx.x;
    const int wid = tid >> 5, lane = tid & 31;

    float vm[4], cm[4];
    float mx = -3.4e38f;
    #pragma unroll
    for (int r = 0; r < 4; r++) {
        const int t = tid + 256 * r;
        const float c = c_mask[n * 1024 + t];
        const float v = g_Smax[n * 1024 + t] * c;
        vm[r] = v; cm[r] = c;
        mx = fmaxf(mx, v);
    }
    #pragma unroll
    for (int o = 16; o > 0; o >>= 1) mx = fmaxf(mx, __shfl_xor_sync(0xffffffffu, mx, o));
    if (lane == 0) redA[wid] = mx;
    __syncthreads();
    mx = redA[0];
    #pragma unroll
    for (int i = 1; i < 8; i++) mx = fmaxf(mx, redA[i]);

    float E = 0.f, M = 0.f, ev[4];
    #pragma unroll
    for (int r = 0; r < 4; r++) {
        const float e = __expf(vm[r] - mx);
        ev[r] = e; E += e; M += e * cm[r];
    }
    #pragma unroll
    for (int o = 16; o > 0; o >>= 1) {
        E += __shfl_xor_sync(0xffffffffu, E, o);
        M += __shfl_xor_sync(0xffffffffu, M, o);
    }
    if (lane == 0) { redB[wid] = E; redC[wid] = M; }
    __syncthreads();
    E = 0.f; M = 0.f;
    #pragma unroll
    for (int i = 0; i < 8; i++) { E += redB[i]; M += redC[i]; }
    const float inv = 1.0f / (M + 1e-13f * E);
    #pragma unroll
    for (int r = 0; r < 4; r++) sa[tid + 256 * r] = ev[r] * cm[r] * inv;
    __syncthreads();

    if (tid < 200) {
        const float* hp = H + (size_t)n * 204800 + tid;
        float accv = 0.f;
        #pragma unroll 8
        for (int t = 0; t < 1024; t++) accv += sa[t] * hp[(size_t)t * 200];
        g_Hbar[n * 200 + tid] = accv;
    }
}

// ---- kernel 3: G[:,:,600:800] = H * Hbar ----
__global__ void __launch_bounds__(256)
bi_attn_hh(const float* __restrict__ H, float* __restrict__ G)
{
    const int idx = blockIdx.x * 256 + threadIdx.x;   // < 64*1024*50
    const int r = idx / 50;
    const int c = idx - r * 50;
    const int n = r >> 10;
    const float4 h4 = *(const float4*)(H + (size_t)r * 200 + c * 4);
    const float4 hb = *(const float4*)(g_Hbar + n * 200 + c * 4);
    float4 o;
    o.x = h4.x * hb.x; o.y = h4.y * hb.y; o.z = h4.z * hb.z; o.w = h4.w * hb.w;
    *(float4*)(G + (size_t)r * 800 + 600 + c * 4) = o;
}

extern "C" void kernel_launch(void* const* d_in, const int* in_sizes, int n_in,
                              void* d_out, int out_size)
{
    const float* H      = (const float*)d_in[0];
    const float* U      = (const float*)d_in[1];
    const float* c_mask = (const float*)d_in[2];
    const float* q_mask = (const float*)d_in[3];
    const float* w      = (const float*)d_in[4];
    const float* b      = (const float*)d_in[5];
    float* G = (float*)d_out;

    cudaFuncSetAttribute(bi_attn_main, cudaFuncAttributeMaxDynamicSharedMemorySize, SMEM_BYTES);

    dim3 g1(8, 64);
    bi_attn_main<<<g1, 256, SMEM_BYTES>>>(H, U, q_mask, w, b, G);
    bi_attn_ctx<<<64, 256>>>(H, c_mask);
    bi_attn_hh<<<(64 * 1024 * 50) / 256, 256>>>(H, G);
}